// round 8
// baseline (speedup 1.0000x reference)
#include <cuda_runtime.h>
#include <cuda_fp16.h>
#include <cstdint>

// ---------------- problem constants -------------------------------------
#define B_    4
#define S_    8192
#define D_    2048
#define HD_   128
#define NTOK  (B_ * S_)            // 32768 tokens
#define NCOL  512                  // 4 projections * HD
#define NBLK  (B_ * (S_ / 4))      // 8192 output blocks
#define OUT_ELEMS (NBLK * HD_)     // 1048576

// ---------------- work split: HMMA (tensor) vs SIMT (f32x2 fma pipe) -----
#define MT_SIMT 73                             // m-tiles (of 64 rows) on SIMT path
#define MT_HMMA (512 - MT_SIMT)                // 439
#define H_CTAS  (MT_HMMA * 4)                  // 1756  (BM64 x BN128)
#define S_CTAS  (MT_SIMT * 2 * 4)              // 584   (BM32 x BN128)
#define GRID    (H_CTAS + S_CTAS)              // 2340
#define ROW_SIMT0 (MT_HMMA * 64)               // 28096

// HMMA tiling: BM=64, BN=128, BK=32
#define NKC   (D_ / 32)            // 64 chunks
// SIMT tiling: BM=32, BN=128, BK=32
#define NKC2  (D_ / 32)            // 64 chunks

// ---------------- scratch (static device globals) ------------------------
__device__ __half g_Wt[NCOL * D_];                // 2 MB, K-major fp16 weights
__device__ __half g_C[(size_t)NTOK * NCOL];       // 32 MB GEMM output (fp16)

// ---------------- helpers ------------------------------------------------
__device__ __forceinline__ uint32_t smem_to_u32(const void* p) {
    uint32_t a;
    asm("{ .reg .u64 t; cvta.to.shared.u64 t, %1; cvt.u32.u64 %0, t; }"
        : "=r"(a) : "l"(p));
    return a;
}

// pack (k0, k1) -> f16x2 with k0 in the low half
__device__ __forceinline__ uint32_t pack2(float k0, float k1) {
    uint32_t r;
    asm("cvt.rn.f16x2.f32 %0, %1, %2;" : "=r"(r) : "f"(k1), "f"(k0));
    return r;
}

#define CP_ASYNC16(dst_u32, src_ptr) \
    asm volatile("cp.async.cg.shared.global [%0], [%1], 16;" \
                 :: "r"(dst_u32), "l"(src_ptr) : "memory")
#define CP_ASYNC_COMMIT() asm volatile("cp.async.commit_group;" ::: "memory")
#define CP_ASYNC_WAIT0()  asm volatile("cp.async.wait_group 0;" ::: "memory")

#define MMA_FP16(d, a, b) \
    asm volatile("mma.sync.aligned.m16n8k16.row.col.f32.f16.f16.f32 " \
                 "{%0,%1,%2,%3}, {%4,%5,%6,%7}, {%8,%9}, {%0,%1,%2,%3};" \
                 : "+f"((d)[0]), "+f"((d)[1]), "+f"((d)[2]), "+f"((d)[3]) \
                 : "r"((a)[0]), "r"((a)[1]), "r"((a)[2]), "r"((a)[3]), \
                   "r"((b)[0]), "r"((b)[1]))

// packed dual-fp32 FMA (Blackwell f32x2 pipe)
#define FFMA2(acc, a, b) \
    asm("fma.rn.f32x2 %0, %1, %2, %0;" : "+l"(acc) : "l"(a), "l"(b))

__device__ __forceinline__ unsigned long long dup64(float x) {
    unsigned long long d;
    asm("mov.b64 %0, {%1, %1};" : "=l"(d) : "r"(__float_as_uint(x)));
    return d;
}
__device__ __forceinline__ void unpack64(unsigned long long d, uint32_t& lo, uint32_t& hi) {
    asm("mov.b64 {%0, %1}, %2;" : "=r"(lo), "=r"(hi) : "l"(d));
}
#define LDS_V2U64(a0, a1, addr) \
    asm("ld.shared.v2.u64 {%0, %1}, [%2];" : "=l"(a0), "=l"(a1) : "r"(addr))
#define LDS_U64(a0, addr) \
    asm("ld.shared.u64 %0, [%1];" : "=l"(a0) : "r"(addr))
#define STS_U64(addr, v) \
    asm volatile("st.shared.u64 [%0], %1;" :: "r"(addr), "l"(v) : "memory")

// ---------------- smem layout --------------------------------------------
// common stage stride (max of both paths), double buffered; 16B-aligned
#define SSTRIDE 25600
#define SMEM_BYTES (2 * SSTRIDE)    // 51200
// HMMA within a stage: fp16 rows 64B padded to 80B
#define H_ROWB  80
#define H_OFF_A 0                   // 64 rows  -> 5120 B
#define H_OFF_B 5120                // 128 rows -> 10240 B  (stage end 15360)
// SIMT within a stage:
//  A: [k][m] fp32 dup-pairs, 32 k-rows x (32 m * 8B = 256B) padded to 272B (16-mult)
//  B: [k][n] fp32, 32 k-rows x (128 * 4B = 512B) padded to 528B
#define S_AROW  272
#define S_OFF_B 8704                // 32*272, 16-aligned
#define S_BROW  528                 // stage end 8704 + 16896 = 25600

// ---------------- kernel 1: coalesced fp16 transpose of weights ----------
__global__ void prep_w_kernel(const float* __restrict__ wka,
                              const float* __restrict__ wkb,
                              const float* __restrict__ wza,
                              const float* __restrict__ wzb)
{
    __shared__ float tile[32][33];
    const int mat = blockIdx.z;
    const float* w = (mat == 0) ? wka : (mat == 1) ? wkb : (mat == 2) ? wza : wzb;
    const int k0 = blockIdx.x * 32;
    const int j0 = blockIdx.y * 32;
    const int tx = threadIdx.x;
    const int ty = threadIdx.y;

    #pragma unroll
    for (int i = 0; i < 32; i += 8)
        tile[ty + i][tx] = w[(size_t)(k0 + ty + i) * HD_ + j0 + tx];
    __syncthreads();
    #pragma unroll
    for (int i = 0; i < 32; i += 8)
        g_Wt[(size_t)(mat * HD_ + j0 + ty + i) * D_ + k0 + tx] =
            __float2half_rn(tile[tx][ty + i]);
}

// ---------------- kernel 2: hybrid GEMM ----------------------------------
// C[t, 0:512] = h[t, :] @ [Wkva | Wkvb | Wza | Wzb]
__global__ void __launch_bounds__(256, 3)
gemm_kernel(const float* __restrict__ h,
            const float* __restrict__ wka, const float* __restrict__ wkb,
            const float* __restrict__ wza, const float* __restrict__ wzb)
{
    extern __shared__ char sm[];
    const uint32_t smem_base = smem_to_u32(sm);
    const int tid = threadIdx.x;
    const int idx = blockIdx.x;

    // ---- interleaved CTA mapping: 3 HMMA : 1 SIMT ----
    int hid = -1, sid = -1;
    if (idx < 2336) {
        int g = idx >> 2, r = idx & 3;
        if (r < 3) hid = 3 * g + r; else sid = g;
    } else {
        hid = 1752 + (idx - 2336);
    }

    if (hid >= 0) {
        // ================= HMMA path: 64 x 128 tile =================
        const int lane   = tid & 31;
        const int wid    = tid >> 5;
        const int warp_m = wid >> 2;          // 0..1  (32 rows)
        const int warp_n = wid & 3;           // 0..3  (32 cols)
        const int t0 = (hid >> 2) * 64;
        const int n0 = (hid & 3) * 128;

        const int arow = tid >> 2;            // 0..63
        const int akc  = tid & 3;             // 8-float k chunk
        const float* hrow = h + (size_t)(t0 + arow) * D_ + akc * 8;
        const uint32_t a_sts = (uint32_t)(arow * H_ROWB + akc * 16);

        float4 v0, v1;
        // prologue
        {
            v0 = *(const float4*)(hrow);
            v1 = *(const float4*)(hrow + 4);
            #pragma unroll
            for (int j = 0; j < 2; ++j) {
                int e = tid + j * 256;
                int row = e >> 2, kc = e & 3;
                uint32_t dst = smem_base + H_OFF_B + (uint32_t)(row * H_ROWB + kc * 16);
                CP_ASYNC16(dst, g_Wt + (size_t)(n0 + row) * D_ + kc * 8);
            }
            CP_ASYNC_COMMIT();
            uint4 q;
            q.x = pack2(v0.x, v0.y); q.y = pack2(v0.z, v0.w);
            q.z = pack2(v1.x, v1.y); q.w = pack2(v1.z, v1.w);
            *(uint4*)(sm + H_OFF_A + a_sts) = q;
            CP_ASYNC_WAIT0();
            __syncthreads();
        }

        float acc[2][4][4];
        #pragma unroll
        for (int mt = 0; mt < 2; ++mt)
            #pragma unroll
            for (int nt = 0; nt < 4; ++nt)
                #pragma unroll
                for (int i = 0; i < 4; ++i) acc[mt][nt][i] = 0.0f;

        const int fr  = lane >> 2;
        const int fco = (lane & 3) * 4;

        for (int c = 0; c < NKC; ++c) {
            const int sb = (c & 1) * SSTRIDE;
            const int nb = sb ^ SSTRIDE;

            if (c + 1 < NKC) {
                const int k1 = (c + 1) * 32;
                v0 = *(const float4*)(hrow + k1);
                v1 = *(const float4*)(hrow + k1 + 4);
                #pragma unroll
                for (int j = 0; j < 2; ++j) {
                    int e = tid + j * 256;
                    int row = e >> 2, kc = e & 3;
                    uint32_t dst = smem_base + nb + H_OFF_B + (uint32_t)(row * H_ROWB + kc * 16);
                    CP_ASYNC16(dst, g_Wt + (size_t)(n0 + row) * D_ + k1 + kc * 8);
                }
                CP_ASYNC_COMMIT();
            }

            #pragma unroll
            for (int ks = 0; ks < 2; ++ks) {
                const int kb = ks * 32 + fco;
                uint32_t af[2][4], bf[4][2];
                #pragma unroll
                for (int mt = 0; mt < 2; ++mt) {
                    const char* p = sm + sb + H_OFF_A + (warp_m * 32 + mt * 16 + fr) * H_ROWB + kb;
                    af[mt][0] = *(const uint32_t*)(p);
                    af[mt][1] = *(const uint32_t*)(p + 8 * H_ROWB);
                    af[mt][2] = *(const uint32_t*)(p + 16);
                    af[mt][3] = *(const uint32_t*)(p + 8 * H_ROWB + 16);
                }
                #pragma unroll
                for (int nt = 0; nt < 4; ++nt) {
                    const char* p = sm + sb + H_OFF_B + (warp_n * 32 + nt * 8 + fr) * H_ROWB + kb;
                    bf[nt][0] = *(const uint32_t*)(p);
                    bf[nt][1] = *(const uint32_t*)(p + 16);
                }
                #pragma unroll
                for (int mt = 0; mt < 2; ++mt)
                    #pragma unroll
                    for (int nt = 0; nt < 4; ++nt)
                        MMA_FP16(acc[mt][nt], af[mt], bf[nt]);
            }

            if (c + 1 < NKC) {
                uint4 q;
                q.x = pack2(v0.x, v0.y); q.y = pack2(v0.z, v0.w);
                q.z = pack2(v1.x, v1.y); q.w = pack2(v1.z, v1.w);
                *(uint4*)(sm + nb + H_OFF_A + a_sts) = q;
                CP_ASYNC_WAIT0();
            }
            __syncthreads();
        }

        #pragma unroll
        for (int mt = 0; mt < 2; ++mt) {
            int r0 = t0 + warp_m * 32 + mt * 16 + fr;
            #pragma unroll
            for (int nt = 0; nt < 4; ++nt) {
                int cb = n0 + warp_n * 32 + nt * 8 + (lane & 3) * 2;
                *(uint32_t*)(g_C + (size_t)r0 * NCOL + cb) =
                    pack2(acc[mt][nt][0], acc[mt][nt][1]);
                *(uint32_t*)(g_C + (size_t)(r0 + 8) * NCOL + cb) =
                    pack2(acc[mt][nt][2], acc[mt][nt][3]);
            }
        }
    } else {
        // ================= SIMT f32x2 path: 32 x 128 tile =================
        const int m0 = ROW_SIMT0 + (sid >> 2) * 32;
        const int nt = sid & 3;
        const float* wsrc = (nt == 0) ? wka : (nt == 1) ? wkb : (nt == 2) ? wza : wzb;
        const int tm = tid >> 5;              // 0..7  (4 rows each)
        const int tn = tid & 31;              // 0..31 (2 n-pairs)

        // producer coords
        const int prow = tid >> 3;            // 0..31
        const int pkq  = tid & 7;             // 4-float k chunk
        const float* ha = h + (size_t)(m0 + prow) * D_ + pkq * 4;

        float4 va;
        // prologue stage 0
        {
            va = *(const float4*)(ha);
            #pragma unroll
            for (int i = 0; i < 4; ++i) {
                int e = tid + i * 256;
                int kk = e >> 5, ch = e & 31;
                uint32_t dst = smem_base + S_OFF_B + (uint32_t)(kk * S_BROW + ch * 16);
                CP_ASYNC16(dst, wsrc + (size_t)kk * HD_ + ch * 4);
            }
            CP_ASYNC_COMMIT();
            uint32_t ab = smem_base + (uint32_t)(pkq * 4) * S_AROW + prow * 8;
            STS_U64(ab,              dup64(va.x));
            STS_U64(ab + S_AROW,     dup64(va.y));
            STS_U64(ab + 2 * S_AROW, dup64(va.z));
            STS_U64(ab + 3 * S_AROW, dup64(va.w));
            CP_ASYNC_WAIT0();
            __syncthreads();
        }

        unsigned long long acc[4][2];
        #pragma unroll
        for (int m = 0; m < 4; ++m) { acc[m][0] = 0ull; acc[m][1] = 0ull; }

        for (int c = 0; c < NKC2; ++c) {
            const int sb = (c & 1) * SSTRIDE;
            const int nb = sb ^ SSTRIDE;

            if (c + 1 < NKC2) {
                const int k1 = (c + 1) * 32;
                va = *(const float4*)(ha + k1);
                #pragma unroll
                for (int i = 0; i < 4; ++i) {
                    int e = tid + i * 256;
                    int kk = e >> 5, ch = e & 31;
                    uint32_t dst = smem_base + nb + S_OFF_B + (uint32_t)(kk * S_BROW + ch * 16);
                    CP_ASYNC16(dst, wsrc + (size_t)(k1 + kk) * HD_ + ch * 4);
                }
                CP_ASYNC_COMMIT();
            }

            const uint32_t abase = smem_base + sb + tm * 32;
            const uint32_t bbase = smem_base + sb + S_OFF_B + tn * 8;
            #pragma unroll
            for (int kk = 0; kk < 32; ++kk) {
                unsigned long long a0, a1, a2, a3, b0, b1;
                LDS_V2U64(a0, a1, abase + kk * S_AROW);
                LDS_V2U64(a2, a3, abase + kk * S_AROW + 16);
                LDS_U64(b0, bbase + kk * S_BROW);
                LDS_U64(b1, bbase + kk * S_BROW + 256);
                FFMA2(acc[0][0], a0, b0); FFMA2(acc[0][1], a0, b1);
                FFMA2(acc[1][0], a1, b0); FFMA2(acc[1][1], a1, b1);
                FFMA2(acc[2][0], a2, b0); FFMA2(acc[2][1], a2, b1);
                FFMA2(acc[3][0], a3, b0); FFMA2(acc[3][1], a3, b1);
            }

            if (c + 1 < NKC2) {
                uint32_t ab = smem_base + nb + (uint32_t)(pkq * 4) * S_AROW + prow * 8;
                STS_U64(ab,              dup64(va.x));
                STS_U64(ab + S_AROW,     dup64(va.y));
                STS_U64(ab + 2 * S_AROW, dup64(va.z));
                STS_U64(ab + 3 * S_AROW, dup64(va.w));
                CP_ASYNC_WAIT0();
            }
            __syncthreads();
        }

        // writeback (fp16)
        #pragma unroll
        for (int m = 0; m < 4; ++m) {
            int row = m0 + tm * 4 + m;
            #pragma unroll
            for (int j = 0; j < 2; ++j) {
                uint32_t lo, hi;
                unpack64(acc[m][j], lo, hi);
                int n = nt * 128 + 2 * tn + 64 * j;
                *(uint32_t*)(g_C + (size_t)row * NCOL + n) =
                    pack2(__uint_as_float(lo), __uint_as_float(hi));
            }
        }
    }
}

// ---------------- kernel 3: masked softmax compression -------------------
// C columns: [0,128)=c_a, [128,256)=c_b, [256,384)=z_a, [384,512)=z_b
__global__ void epilogue_kernel(const float* __restrict__ b_a,
                                const float* __restrict__ b_b,
                                float* __restrict__ out, int dup)
{
    int g  = blockIdx.x * blockDim.x + threadIdx.x;   // 0..1048575
    int d  = g & 127;
    int bi = g >> 7;           // global block id 0..8191
    int i  = bi & 2047;        // block within batch
    int b  = bi >> 11;         // batch
    int t0 = b * S_ + i * 4;   // first token of current block

    float logit[8], val[8];
    const bool has_prev = (i > 0);
    #pragma unroll
    for (int j = 0; j < 4; ++j) {
        if (has_prev) {
            const __half* Cp = g_C + (size_t)(t0 - 4 + j) * NCOL;
            logit[j] = __half2float(Cp[384 + d]) + b_b[j * 128 + d];
            val[j]   = __half2float(Cp[128 + d]);
        } else {
            logit[j] = -3.0e38f;
            val[j]   = 0.0f;
        }
        const __half* Cc = g_C + (size_t)(t0 + j) * NCOL;
        logit[4 + j] = __half2float(Cc[256 + d]) + b_a[j * 128 + d];
        val[4 + j]   = __half2float(Cc[d]);
    }
    float mx = logit[0];
    #pragma unroll
    for (int j = 1; j < 8; ++j) mx = fmaxf(mx, logit[j]);
    float s = 0.0f, acc = 0.0f;
    #pragma unroll
    for (int j = 0; j < 8; ++j) {
        float e = __expf(logit[j] - mx);
        s   += e;
        acc += e * val[j];
    }
    float r = acc / s;
    out[g] = r;
    if (dup) out[g + OUT_ELEMS] = r;
}

// ---------------- launch ------------------------------------------------
extern "C" void kernel_launch(void* const* d_in, const int* in_sizes, int n_in,
                              void* d_out, int out_size)
{
    const float* h   = (const float*)d_in[0];
    const float* wka = (const float*)d_in[1];
    const float* wkb = (const float*)d_in[2];
    const float* wza = (const float*)d_in[3];
    const float* wzb = (const float*)d_in[4];
    const float* ba  = (const float*)d_in[5];
    const float* bb  = (const float*)d_in[6];
    float* out = (float*)d_out;

    cudaFuncSetAttribute(gemm_kernel,
                         cudaFuncAttributeMaxDynamicSharedMemorySize, SMEM_BYTES);

    prep_w_kernel<<<dim3(D_ / 32, HD_ / 32, 4), dim3(32, 8)>>>(wka, wkb, wza, wzb);
    gemm_kernel<<<GRID, 256, SMEM_BYTES>>>(h, wka, wkb, wza, wzb);

    int dup = (out_size >= 2 * OUT_ELEMS) ? 1 : 0;
    epilogue_kernel<<<OUT_ELEMS / 256, 256>>>(ba, bb, out, dup);
}

// round 9
// speedup vs baseline: 1.0103x; 1.0103x over previous
#include <cuda_runtime.h>
#include <cuda_fp16.h>
#include <cstdint>

// ---------------- problem constants -------------------------------------
#define B_    4
#define S_    8192
#define D_    2048
#define HD_   128
#define NTOK  (B_ * S_)            // 32768 tokens
#define NCOL  512                  // 4 projections * HD
#define NBLK  (B_ * (S_ / 4))      // 8192 output blocks
#define OUT_ELEMS (NBLK * HD_)     // 1048576

// ---------------- work split: HMMA (tensor) vs SIMT (f32x2 fma pipe) -----
#define MT_SIMT 73                             // m-tiles (of 64 rows) on SIMT path
#define MT_HMMA (512 - MT_SIMT)                // 439
#define H_CTAS  (MT_HMMA * 4)                  // 1756  (BM64 x BN128)
#define S_CTAS  (MT_SIMT * 2 * 4)              // 584   (BM32 x BN128)
#define GRID    (H_CTAS + S_CTAS)              // 2340
#define ROW_SIMT0 (MT_HMMA * 64)               // 28096

// HMMA tiling: BM=64, BN=128, BK=32
#define NKC   (D_ / 32)            // 64 chunks
// SIMT tiling: BM=32, BN=128, BK=32
#define NKC2  (D_ / 32)            // 64 chunks

// ---------------- scratch (static device globals) ------------------------
__device__ __half g_Wt[NCOL * D_];                // 2 MB, K-major fp16 weights
__device__ __half g_C[(size_t)NTOK * NCOL];       // 32 MB GEMM output (fp16)

// ---------------- helpers ------------------------------------------------
__device__ __forceinline__ uint32_t smem_to_u32(const void* p) {
    uint32_t a;
    asm("{ .reg .u64 t; cvta.to.shared.u64 t, %1; cvt.u32.u64 %0, t; }"
        : "=r"(a) : "l"(p));
    return a;
}

// pack (k0, k1) -> f16x2 with k0 in the low half
__device__ __forceinline__ uint32_t pack2(float k0, float k1) {
    uint32_t r;
    asm("cvt.rn.f16x2.f32 %0, %1, %2;" : "=r"(r) : "f"(k1), "f"(k0));
    return r;
}

#define CP_ASYNC16(dst_u32, src_ptr) \
    asm volatile("cp.async.cg.shared.global [%0], [%1], 16;" \
                 :: "r"(dst_u32), "l"(src_ptr) : "memory")
#define CP_ASYNC_COMMIT() asm volatile("cp.async.commit_group;" ::: "memory")
#define CP_ASYNC_WAIT0()  asm volatile("cp.async.wait_group 0;" ::: "memory")

#define MMA_FP16(d, a, b) \
    asm volatile("mma.sync.aligned.m16n8k16.row.col.f32.f16.f16.f32 " \
                 "{%0,%1,%2,%3}, {%4,%5,%6,%7}, {%8,%9}, {%0,%1,%2,%3};" \
                 : "+f"((d)[0]), "+f"((d)[1]), "+f"((d)[2]), "+f"((d)[3]) \
                 : "r"((a)[0]), "r"((a)[1]), "r"((a)[2]), "r"((a)[3]), \
                   "r"((b)[0]), "r"((b)[1]))

// packed dual-fp32 FMA (Blackwell f32x2 pipe)
#define FFMA2(acc, a, b) \
    asm("fma.rn.f32x2 %0, %1, %2, %0;" : "+l"(acc) : "l"(a), "l"(b))

__device__ __forceinline__ unsigned long long dup64(float x) {
    unsigned long long d;
    asm("mov.b64 %0, {%1, %1};" : "=l"(d) : "r"(__float_as_uint(x)));
    return d;
}
__device__ __forceinline__ void unpack64(unsigned long long d, uint32_t& lo, uint32_t& hi) {
    asm("mov.b64 {%0, %1}, %2;" : "=r"(lo), "=r"(hi) : "l"(d));
}
#define LDS_V2U64(a0, a1, addr) \
    asm("ld.shared.v2.u64 {%0, %1}, [%2];" : "=l"(a0), "=l"(a1) : "r"(addr))
#define LDS_U64(a0, addr) \
    asm("ld.shared.u64 %0, [%1];" : "=l"(a0) : "r"(addr))
#define STS_U64(addr, v) \
    asm volatile("st.shared.u64 [%0], %1;" :: "r"(addr), "l"(v) : "memory")

// ---------------- smem layout --------------------------------------------
// common stage stride (max of both paths), double buffered; 16B-aligned
#define SSTRIDE 25600
#define SMEM_BYTES (2 * SSTRIDE)    // 51200
// HMMA within a stage: fp16 rows 64B padded to 80B
#define H_ROWB  80
#define H_OFF_A 0                   // 64 rows  -> 5120 B
#define H_OFF_B 5120                // 128 rows -> 10240 B  (stage end 15360)
// SIMT within a stage:
//  A: [k][m] fp32 dup-pairs, 32 k-rows x (32 m * 8B = 256B) padded to 272B (16-mult)
//  B: [k][n] fp32, 32 k-rows x (128 * 4B = 512B) padded to 528B
#define S_AROW  272
#define S_OFF_B 8704                // 32*272, 16-aligned
#define S_BROW  528                 // stage end 8704 + 16896 = 25600

// ---------------- kernel 1: coalesced fp16 transpose of weights ----------
__global__ void prep_w_kernel(const float* __restrict__ wka,
                              const float* __restrict__ wkb,
                              const float* __restrict__ wza,
                              const float* __restrict__ wzb)
{
    __shared__ float tile[32][33];
    const int mat = blockIdx.z;
    const float* w = (mat == 0) ? wka : (mat == 1) ? wkb : (mat == 2) ? wza : wzb;
    const int k0 = blockIdx.x * 32;
    const int j0 = blockIdx.y * 32;
    const int tx = threadIdx.x;
    const int ty = threadIdx.y;

    #pragma unroll
    for (int i = 0; i < 32; i += 8)
        tile[ty + i][tx] = w[(size_t)(k0 + ty + i) * HD_ + j0 + tx];
    __syncthreads();
    #pragma unroll
    for (int i = 0; i < 32; i += 8)
        g_Wt[(size_t)(mat * HD_ + j0 + ty + i) * D_ + k0 + tx] =
            __float2half_rn(tile[tx][ty + i]);
}

// ---------------- kernel 2: hybrid GEMM ----------------------------------
// C[t, 0:512] = h[t, :] @ [Wkva | Wkvb | Wza | Wzb]
__global__ void __launch_bounds__(256, 3)
gemm_kernel(const float* __restrict__ h,
            const float* __restrict__ wka, const float* __restrict__ wkb,
            const float* __restrict__ wza, const float* __restrict__ wzb)
{
    extern __shared__ char sm[];
    const uint32_t smem_base = smem_to_u32(sm);
    const int tid = threadIdx.x;
    const int idx = blockIdx.x;

    // ---- interleaved CTA mapping: 3 HMMA : 1 SIMT ----
    int hid = -1, sid = -1;
    if (idx < 2336) {
        int g = idx >> 2, r = idx & 3;
        if (r < 3) hid = 3 * g + r; else sid = g;
    } else {
        hid = 1752 + (idx - 2336);
    }

    if (hid >= 0) {
        // ================= HMMA path: 64 x 128 tile =================
        const int lane   = tid & 31;
        const int wid    = tid >> 5;
        const int warp_m = wid >> 2;          // 0..1  (32 rows)
        const int warp_n = wid & 3;           // 0..3  (32 cols)
        const int t0 = (hid >> 2) * 64;
        const int n0 = (hid & 3) * 128;

        const int arow = tid >> 2;            // 0..63
        const int akc  = tid & 3;             // 8-float k chunk
        const float* hrow = h + (size_t)(t0 + arow) * D_ + akc * 8;
        const uint32_t a_sts = (uint32_t)(arow * H_ROWB + akc * 16);

        float4 v0, v1;
        // prologue
        {
            v0 = *(const float4*)(hrow);
            v1 = *(const float4*)(hrow + 4);
            #pragma unroll
            for (int j = 0; j < 2; ++j) {
                int e = tid + j * 256;
                int row = e >> 2, kc = e & 3;
                uint32_t dst = smem_base + H_OFF_B + (uint32_t)(row * H_ROWB + kc * 16);
                CP_ASYNC16(dst, g_Wt + (size_t)(n0 + row) * D_ + kc * 8);
            }
            CP_ASYNC_COMMIT();
            uint4 q;
            q.x = pack2(v0.x, v0.y); q.y = pack2(v0.z, v0.w);
            q.z = pack2(v1.x, v1.y); q.w = pack2(v1.z, v1.w);
            *(uint4*)(sm + H_OFF_A + a_sts) = q;
            CP_ASYNC_WAIT0();
            __syncthreads();
        }

        float acc[2][4][4];
        #pragma unroll
        for (int mt = 0; mt < 2; ++mt)
            #pragma unroll
            for (int nt = 0; nt < 4; ++nt)
                #pragma unroll
                for (int i = 0; i < 4; ++i) acc[mt][nt][i] = 0.0f;

        const int fr  = lane >> 2;
        const int fco = (lane & 3) * 4;

        for (int c = 0; c < NKC; ++c) {
            const int sb = (c & 1) * SSTRIDE;
            const int nb = sb ^ SSTRIDE;

            if (c + 1 < NKC) {
                const int k1 = (c + 1) * 32;
                v0 = *(const float4*)(hrow + k1);
                v1 = *(const float4*)(hrow + k1 + 4);
                #pragma unroll
                for (int j = 0; j < 2; ++j) {
                    int e = tid + j * 256;
                    int row = e >> 2, kc = e & 3;
                    uint32_t dst = smem_base + nb + H_OFF_B + (uint32_t)(row * H_ROWB + kc * 16);
                    CP_ASYNC16(dst, g_Wt + (size_t)(n0 + row) * D_ + k1 + kc * 8);
                }
                CP_ASYNC_COMMIT();
            }

            #pragma unroll
            for (int ks = 0; ks < 2; ++ks) {
                const int kb = ks * 32 + fco;
                uint32_t af[2][4], bf[4][2];
                #pragma unroll
                for (int mt = 0; mt < 2; ++mt) {
                    const char* p = sm + sb + H_OFF_A + (warp_m * 32 + mt * 16 + fr) * H_ROWB + kb;
                    af[mt][0] = *(const uint32_t*)(p);
                    af[mt][1] = *(const uint32_t*)(p + 8 * H_ROWB);
                    af[mt][2] = *(const uint32_t*)(p + 16);
                    af[mt][3] = *(const uint32_t*)(p + 8 * H_ROWB + 16);
                }
                #pragma unroll
                for (int nt = 0; nt < 4; ++nt) {
                    const char* p = sm + sb + H_OFF_B + (warp_n * 32 + nt * 8 + fr) * H_ROWB + kb;
                    bf[nt][0] = *(const uint32_t*)(p);
                    bf[nt][1] = *(const uint32_t*)(p + 16);
                }
                #pragma unroll
                for (int mt = 0; mt < 2; ++mt)
                    #pragma unroll
                    for (int nt = 0; nt < 4; ++nt)
                        MMA_FP16(acc[mt][nt], af[mt], bf[nt]);
            }

            if (c + 1 < NKC) {
                uint4 q;
                q.x = pack2(v0.x, v0.y); q.y = pack2(v0.z, v0.w);
                q.z = pack2(v1.x, v1.y); q.w = pack2(v1.z, v1.w);
                *(uint4*)(sm + nb + H_OFF_A + a_sts) = q;
                CP_ASYNC_WAIT0();
            }
            __syncthreads();
        }

        #pragma unroll
        for (int mt = 0; mt < 2; ++mt) {
            int r0 = t0 + warp_m * 32 + mt * 16 + fr;
            #pragma unroll
            for (int nt = 0; nt < 4; ++nt) {
                int cb = n0 + warp_n * 32 + nt * 8 + (lane & 3) * 2;
                *(uint32_t*)(g_C + (size_t)r0 * NCOL + cb) =
                    pack2(acc[mt][nt][0], acc[mt][nt][1]);
                *(uint32_t*)(g_C + (size_t)(r0 + 8) * NCOL + cb) =
                    pack2(acc[mt][nt][2], acc[mt][nt][3]);
            }
        }
    } else {
        // ================= SIMT f32x2 path: 32 x 128 tile =================
        const int m0 = ROW_SIMT0 + (sid >> 2) * 32;
        const int nt = sid & 3;
        const float* wsrc = (nt == 0) ? wka : (nt == 1) ? wkb : (nt == 2) ? wza : wzb;
        const int tm = tid >> 5;              // 0..7  (4 rows each)
        const int tn = tid & 31;              // 0..31 (2 n-pairs)

        // producer coords
        const int prow = tid >> 3;            // 0..31
        const int pkq  = tid & 7;             // 4-float k chunk
        const float* ha = h + (size_t)(m0 + prow) * D_ + pkq * 4;

        float4 va;
        // prologue stage 0
        {
            va = *(const float4*)(ha);
            #pragma unroll
            for (int i = 0; i < 4; ++i) {
                int e = tid + i * 256;
                int kk = e >> 5, ch = e & 31;
                uint32_t dst = smem_base + S_OFF_B + (uint32_t)(kk * S_BROW + ch * 16);
                CP_ASYNC16(dst, wsrc + (size_t)kk * HD_ + ch * 4);
            }
            CP_ASYNC_COMMIT();
            uint32_t ab = smem_base + (uint32_t)(pkq * 4) * S_AROW + prow * 8;
            STS_U64(ab,              dup64(va.x));
            STS_U64(ab + S_AROW,     dup64(va.y));
            STS_U64(ab + 2 * S_AROW, dup64(va.z));
            STS_U64(ab + 3 * S_AROW, dup64(va.w));
            CP_ASYNC_WAIT0();
            __syncthreads();
        }

        unsigned long long acc[4][2];
        #pragma unroll
        for (int m = 0; m < 4; ++m) { acc[m][0] = 0ull; acc[m][1] = 0ull; }

        for (int c = 0; c < NKC2; ++c) {
            const int sb = (c & 1) * SSTRIDE;
            const int nb = sb ^ SSTRIDE;

            if (c + 1 < NKC2) {
                const int k1 = (c + 1) * 32;
                va = *(const float4*)(ha + k1);
                #pragma unroll
                for (int i = 0; i < 4; ++i) {
                    int e = tid + i * 256;
                    int kk = e >> 5, ch = e & 31;
                    uint32_t dst = smem_base + nb + S_OFF_B + (uint32_t)(kk * S_BROW + ch * 16);
                    CP_ASYNC16(dst, wsrc + (size_t)(k1 + kk) * HD_ + ch * 4);
                }
                CP_ASYNC_COMMIT();
            }

            const uint32_t abase = smem_base + sb + tm * 32;
            const uint32_t bbase = smem_base + sb + S_OFF_B + tn * 8;
            #pragma unroll
            for (int kk = 0; kk < 32; ++kk) {
                unsigned long long a0, a1, a2, a3, b0, b1;
                LDS_V2U64(a0, a1, abase + kk * S_AROW);
                LDS_V2U64(a2, a3, abase + kk * S_AROW + 16);
                LDS_U64(b0, bbase + kk * S_BROW);
                LDS_U64(b1, bbase + kk * S_BROW + 256);
                FFMA2(acc[0][0], a0, b0); FFMA2(acc[0][1], a0, b1);
                FFMA2(acc[1][0], a1, b0); FFMA2(acc[1][1], a1, b1);
                FFMA2(acc[2][0], a2, b0); FFMA2(acc[2][1], a2, b1);
                FFMA2(acc[3][0], a3, b0); FFMA2(acc[3][1], a3, b1);
            }

            if (c + 1 < NKC2) {
                uint32_t ab = smem_base + nb + (uint32_t)(pkq * 4) * S_AROW + prow * 8;
                STS_U64(ab,              dup64(va.x));
                STS_U64(ab + S_AROW,     dup64(va.y));
                STS_U64(ab + 2 * S_AROW, dup64(va.z));
                STS_U64(ab + 3 * S_AROW, dup64(va.w));
                CP_ASYNC_WAIT0();
            }
            __syncthreads();
        }

        // writeback (fp16)
        #pragma unroll
        for (int m = 0; m < 4; ++m) {
            int row = m0 + tm * 4 + m;
            #pragma unroll
            for (int j = 0; j < 2; ++j) {
                uint32_t lo, hi;
                unpack64(acc[m][j], lo, hi);
                int n = nt * 128 + 2 * tn + 64 * j;
                *(uint32_t*)(g_C + (size_t)row * NCOL + n) =
                    pack2(__uint_as_float(lo), __uint_as_float(hi));
            }
        }
    }
}

// ---------------- kernel 3: masked softmax compression -------------------
// C columns: [0,128)=c_a, [128,256)=c_b, [256,384)=z_a, [384,512)=z_b
__global__ void epilogue_kernel(const float* __restrict__ b_a,
                                const float* __restrict__ b_b,
                                float* __restrict__ out, int dup)
{
    int g  = blockIdx.x * blockDim.x + threadIdx.x;   // 0..1048575
    int d  = g & 127;
    int bi = g >> 7;           // global block id 0..8191
    int i  = bi & 2047;        // block within batch
    int b  = bi >> 11;         // batch
    int t0 = b * S_ + i * 4;   // first token of current block

    float logit[8], val[8];
    const bool has_prev = (i > 0);
    #pragma unroll
    for (int j = 0; j < 4; ++j) {
        if (has_prev) {
            const __half* Cp = g_C + (size_t)(t0 - 4 + j) * NCOL;
            logit[j] = __half2float(Cp[384 + d]) + b_b[j * 128 + d];
            val[j]   = __half2float(Cp[128 + d]);
        } else {
            logit[j] = -3.0e38f;
            val[j]   = 0.0f;
        }
        const __half* Cc = g_C + (size_t)(t0 + j) * NCOL;
        logit[4 + j] = __half2float(Cc[256 + d]) + b_a[j * 128 + d];
        val[4 + j]   = __half2float(Cc[d]);
    }
    float mx = logit[0];
    #pragma unroll
    for (int j = 1; j < 8; ++j) mx = fmaxf(mx, logit[j]);
    float s = 0.0f, acc = 0.0f;
    #pragma unroll
    for (int j = 0; j < 8; ++j) {
        float e = __expf(logit[j] - mx);
        s   += e;
        acc += e * val[j];
    }
    float r = acc / s;
    out[g] = r;
    if (dup) out[g + OUT_ELEMS] = r;
}

// ---------------- launch ------------------------------------------------
extern "C" void kernel_launch(void* const* d_in, const int* in_sizes, int n_in,
                              void* d_out, int out_size)
{
    const float* h   = (const float*)d_in[0];
    const float* wka = (const float*)d_in[1];
    const float* wkb = (const float*)d_in[2];
    const float* wza = (const float*)d_in[3];
    const float* wzb = (const float*)d_in[4];
    const float* ba  = (const float*)d_in[5];
    const float* bb  = (const float*)d_in[6];
    float* out = (float*)d_out;

    cudaFuncSetAttribute(gemm_kernel,
                         cudaFuncAttributeMaxDynamicSharedMemorySize, SMEM_BYTES);

    prep_w_kernel<<<dim3(D_ / 32, HD_ / 32, 4), dim3(32, 8)>>>(wka, wkb, wza, wzb);
    gemm_kernel<<<GRID, 256, SMEM_BYTES>>>(h, wka, wkb, wza, wzb);

    int dup = (out_size >= 2 * OUT_ELEMS) ? 1 : 0;
    epilogue_kernel<<<OUT_ELEMS / 256, 256>>>(ba, bb, out, dup);
}

// round 10
// speedup vs baseline: 2.6017x; 2.5751x over previous
#include <cuda_runtime.h>
#include <cuda_fp16.h>
#include <cstdint>

// ---------------- problem constants -------------------------------------
#define B_    4
#define S_    8192
#define D_    2048
#define HD_   128
#define NTOK  (B_ * S_)            // 32768 tokens
#define NCOL  512                  // 4 projections * HD
#define NBLK  (B_ * (S_ / 4))      // 8192 output blocks
#define OUT_ELEMS (NBLK * HD_)     // 1048576

// GEMM tiling
#define BM 64
#define BN 256
#define BK 64
#define NKC (D_ / BK)              // 32 k-chunks

// ---------------- scratch (static device globals) ------------------------
__device__ __half g_Wt[NCOL * D_];                // 2 MB, K-major fp16 weights
__device__ __half g_C[(size_t)NTOK * NCOL];       // 32 MB GEMM output (fp16)

// ---------------- helpers ------------------------------------------------
__device__ __forceinline__ uint32_t smem_to_u32(const void* p) {
    uint32_t a;
    asm("{ .reg .u64 t; cvta.to.shared.u64 t, %1; cvt.u32.u64 %0, t; }"
        : "=r"(a) : "l"(p));
    return a;
}

// pack (k0, k1) -> f16x2 with k0 in the low half
__device__ __forceinline__ uint32_t pack2(float k0, float k1) {
    uint32_t r;
    asm("cvt.rn.f16x2.f32 %0, %1, %2;" : "=r"(r) : "f"(k1), "f"(k0));
    return r;
}

#define CP_ASYNC16(dst_u32, src_ptr) \
    asm volatile("cp.async.cg.shared.global [%0], [%1], 16;" \
                 :: "r"(dst_u32), "l"(src_ptr) : "memory")
#define CP_ASYNC_COMMIT() asm volatile("cp.async.commit_group;" ::: "memory")
#define CP_ASYNC_WAIT0()  asm volatile("cp.async.wait_group 0;" ::: "memory")

#define MMA_FP16(d, a, b) \
    asm volatile("mma.sync.aligned.m16n8k16.row.col.f32.f16.f16.f32 " \
                 "{%0,%1,%2,%3}, {%4,%5,%6,%7}, {%8,%9}, {%0,%1,%2,%3};" \
                 : "+f"((d)[0]), "+f"((d)[1]), "+f"((d)[2]), "+f"((d)[3]) \
                 : "r"((a)[0]), "r"((a)[1]), "r"((a)[2]), "r"((a)[3]), \
                   "r"((b)[0]), "r"((b)[1]))

#define LDMATRIX_X4(r0, r1, r2, r3, addr) \
    asm volatile("ldmatrix.sync.aligned.m8n8.x4.shared.b16 {%0,%1,%2,%3}, [%4];" \
                 : "=r"(r0), "=r"(r1), "=r"(r2), "=r"(r3) : "r"(addr))

// ---------------- smem layout (bytes): fp16 tiles, 128B rows padded to 144B
#define ROWB    144
#define A_PLANE (64 * ROWB)                // 9216 B
#define B_PLANE (256 * ROWB)               // 36864 B
#define STAGE   (A_PLANE + B_PLANE)        // 46080 B
#define OFF_A   0
#define OFF_B   A_PLANE
#define SMEM_BYTES (2 * STAGE)             // 92160 B

// ---------------- kernel 1: coalesced fp16 transpose of weights ----------
// g_Wt[n, k] = w_mat[k, j],  n = mat*128 + j
__global__ void prep_w_kernel(const float* __restrict__ wka,
                              const float* __restrict__ wkb,
                              const float* __restrict__ wza,
                              const float* __restrict__ wzb)
{
    __shared__ float tile[32][33];
    const int mat = blockIdx.z;
    const float* w = (mat == 0) ? wka : (mat == 1) ? wkb : (mat == 2) ? wza : wzb;
    const int k0 = blockIdx.x * 32;
    const int j0 = blockIdx.y * 32;
    const int tx = threadIdx.x;       // 0..31
    const int ty = threadIdx.y;       // 0..7

    #pragma unroll
    for (int i = 0; i < 32; i += 8)
        tile[ty + i][tx] = w[(size_t)(k0 + ty + i) * HD_ + j0 + tx];
    __syncthreads();
    #pragma unroll
    for (int i = 0; i < 32; i += 8)
        g_Wt[(size_t)(mat * HD_ + j0 + ty + i) * D_ + k0 + tx] =
            __float2half_rn(tile[tx][ty + i]);
}

// ---------------- kernel 2: pipelined fp16 mma.sync GEMM -----------------
// C[t, 0:512] = h[t, :] @ [Wkva | Wkvb | Wza | Wzb]
__global__ void __launch_bounds__(256, 2)
gemm_kernel(const float* __restrict__ h)
{
    extern __shared__ char sm[];
    const uint32_t smem_base = smem_to_u32(sm);

    const int tid    = threadIdx.x;
    const int lane   = tid & 31;
    const int wid    = tid >> 5;
    const int warp_m = wid >> 2;          // 0..1  (32 rows each)
    const int warp_n = wid & 3;           // 0..3  (64 cols each)

    const int t0 = (int)(blockIdx.x >> 1) * BM;
    const int n0 = (int)(blockIdx.x & 1) * BN;

    // A load coords: thread covers 16 contiguous k, one row
    const int arow = tid >> 2;            // 0..63
    const int akc  = tid & 3;             // 16-element k-chunk within 64
    const float* hrow = h + (size_t)(t0 + arow) * D_ + akc * 16;
    const uint32_t a_sts = (uint32_t)(arow * ROWB + akc * 32);

    uint32_t qa[8];

    // quantize 16 floats from hrow+off into qa
    auto loadquantA = [&](int koff) {
        #pragma unroll
        for (int i = 0; i < 4; ++i) {
            float4 v = *(const float4*)(hrow + koff + i * 4);
            qa[2 * i]     = pack2(v.x, v.y);
            qa[2 * i + 1] = pack2(v.z, v.w);
        }
    };

    // -------- prologue: stage 0 --------
    {
        loadquantA(0);
        #pragma unroll
        for (int j = 0; j < 8; ++j) {
            int e = tid + j * 256;
            int row = e >> 3, kc = e & 7;
            uint32_t dst = smem_base + OFF_B + (uint32_t)(row * ROWB + kc * 16);
            CP_ASYNC16(dst, g_Wt + (size_t)(n0 + row) * D_ + kc * 8);
        }
        CP_ASYNC_COMMIT();
        *(uint4*)(sm + OFF_A + a_sts)      = *(uint4*)(qa);
        *(uint4*)(sm + OFF_A + a_sts + 16) = *(uint4*)(qa + 4);
        CP_ASYNC_WAIT0();
        __syncthreads();
    }

    float acc[2][8][4];
    #pragma unroll
    for (int mt = 0; mt < 2; ++mt)
        #pragma unroll
        for (int nt = 0; nt < 8; ++nt)
            #pragma unroll
            for (int i = 0; i < 4; ++i) acc[mt][nt][i] = 0.0f;

    // ---- ldmatrix per-lane base addresses (stage offset added at use) ----
    // A tiles (m16k16, x4): lanes 0-7 rows m0-7 +0B; 8-15 rows m8-15 +0B;
    //                       16-23 rows m0-7 +16B; 24-31 rows m8-15 +16B
    const int aL_row = (lane & 7) + 8 * ((lane >> 3) & 1);
    const int aL_off = 16 * ((lane >> 4) & 1);
    uint32_t a_addr[2];
    #pragma unroll
    for (int mt = 0; mt < 2; ++mt)
        a_addr[mt] = smem_base + OFF_A +
                     (uint32_t)((warp_m * 32 + mt * 16 + aL_row) * ROWB + aL_off);

    // B tiles (two n8k16 per x4): matrices {nt+0B, nt+16B, nt+1+0B, nt+1+16B}
    const int bL_row = (lane & 7) + 8 * ((lane >> 4) & 1);   // which nt of the pair
    const int bL_off = 16 * ((lane >> 3) & 1);
    uint32_t b_addr[4];
    #pragma unroll
    for (int j = 0; j < 4; ++j)
        b_addr[j] = smem_base + OFF_B +
                    (uint32_t)((warp_n * 64 + j * 16 + bL_row) * ROWB + bL_off);

    for (int c = 0; c < NKC; ++c) {
        const int sb = (c & 1) * STAGE;
        const int nb = sb ^ STAGE;

        if (c + 1 < NKC) {
            const int k1 = (c + 1) * BK;
            loadquantA(k1);
            #pragma unroll
            for (int j = 0; j < 8; ++j) {
                int e = tid + j * 256;
                int row = e >> 3, kc = e & 7;
                uint32_t dst = smem_base + nb + OFF_B + (uint32_t)(row * ROWB + kc * 16);
                CP_ASYNC16(dst, g_Wt + (size_t)(n0 + row) * D_ + k1 + kc * 8);
            }
            CP_ASYNC_COMMIT();
        }

        // -------- compute on stage sb: 4 k16-steps --------
        #pragma unroll
        for (int ks = 0; ks < 4; ++ks) {
            const uint32_t ko = (uint32_t)sb + ks * 32;
            uint32_t af[2][4], bf[8][2];
            LDMATRIX_X4(af[0][0], af[0][1], af[0][2], af[0][3], a_addr[0] + ko);
            LDMATRIX_X4(af[1][0], af[1][1], af[1][2], af[1][3], a_addr[1] + ko);
            #pragma unroll
            for (int j = 0; j < 4; ++j)
                LDMATRIX_X4(bf[2 * j][0], bf[2 * j][1],
                            bf[2 * j + 1][0], bf[2 * j + 1][1], b_addr[j] + ko);
            #pragma unroll
            for (int mt = 0; mt < 2; ++mt)
                #pragma unroll
                for (int nt = 0; nt < 8; ++nt)
                    MMA_FP16(acc[mt][nt], af[mt], bf[nt]);
        }

        if (c + 1 < NKC) {
            *(uint4*)(sm + nb + OFF_A + a_sts)      = *(uint4*)(qa);
            *(uint4*)(sm + nb + OFF_A + a_sts + 16) = *(uint4*)(qa + 4);
            CP_ASYNC_WAIT0();
        }
        __syncthreads();
    }

    // -------- writeback (fp16) --------
    const int fr = lane >> 2;
    #pragma unroll
    for (int mt = 0; mt < 2; ++mt) {
        int r0 = t0 + warp_m * 32 + mt * 16 + fr;
        #pragma unroll
        for (int nt = 0; nt < 8; ++nt) {
            int cb = n0 + warp_n * 64 + nt * 8 + (lane & 3) * 2;
            *(uint32_t*)(g_C + (size_t)r0 * NCOL + cb) =
                pack2(acc[mt][nt][0], acc[mt][nt][1]);
            *(uint32_t*)(g_C + (size_t)(r0 + 8) * NCOL + cb) =
                pack2(acc[mt][nt][2], acc[mt][nt][3]);
        }
    }
}

// ---------------- kernel 3: masked softmax compression (half2) -----------
// C columns: [0,128)=c_a, [128,256)=c_b, [256,384)=z_a, [384,512)=z_b
__global__ void epilogue_kernel(const float* __restrict__ b_a,
                                const float* __restrict__ b_b,
                                float* __restrict__ out, int dup)
{
    int g2 = blockIdx.x * blockDim.x + threadIdx.x;   // 0..524287 (pairs)
    int d  = (g2 & 63) * 2;    // even feature index
    int bi = g2 >> 6;          // global block id 0..8191
    int i  = bi & 2047;        // block within batch
    int b  = bi >> 11;         // batch
    int t0 = b * S_ + i * 4;   // first token of current block

    float2 logit[8], val[8];
    const bool has_prev = (i > 0);
    #pragma unroll
    for (int j = 0; j < 4; ++j) {
        float2 bb2 = *(const float2*)(b_b + j * 128 + d);
        float2 ba2 = *(const float2*)(b_a + j * 128 + d);
        if (has_prev) {
            const __half* Cp = g_C + (size_t)(t0 - 4 + j) * NCOL;
            float2 z = __half22float2(*(const __half2*)(Cp + 384 + d));
            float2 v = __half22float2(*(const __half2*)(Cp + 128 + d));
            logit[j] = make_float2(z.x + bb2.x, z.y + bb2.y);
            val[j]   = v;
        } else {
            logit[j] = make_float2(-3.0e38f, -3.0e38f);
            val[j]   = make_float2(0.0f, 0.0f);
        }
        const __half* Cc = g_C + (size_t)(t0 + j) * NCOL;
        float2 z = __half22float2(*(const __half2*)(Cc + 256 + d));
        float2 v = __half22float2(*(const __half2*)(Cc + d));
        logit[4 + j] = make_float2(z.x + ba2.x, z.y + ba2.y);
        val[4 + j]   = v;
    }
    float mx0 = logit[0].x, mx1 = logit[0].y;
    #pragma unroll
    for (int j = 1; j < 8; ++j) {
        mx0 = fmaxf(mx0, logit[j].x);
        mx1 = fmaxf(mx1, logit[j].y);
    }
    float s0 = 0.0f, s1 = 0.0f, a0 = 0.0f, a1 = 0.0f;
    #pragma unroll
    for (int j = 0; j < 8; ++j) {
        float e0 = __expf(logit[j].x - mx0);
        float e1 = __expf(logit[j].y - mx1);
        s0 += e0; s1 += e1;
        a0 += e0 * val[j].x; a1 += e1 * val[j].y;
    }
    float2 r = make_float2(a0 / s0, a1 / s1);
    int o = bi * 128 + d;
    *(float2*)(out + o) = r;
    if (dup) *(float2*)(out + o + OUT_ELEMS) = r;
}

// ---------------- launch ------------------------------------------------
extern "C" void kernel_launch(void* const* d_in, const int* in_sizes, int n_in,
                              void* d_out, int out_size)
{
    const float* h   = (const float*)d_in[0];
    const float* wka = (const float*)d_in[1];
    const float* wkb = (const float*)d_in[2];
    const float* wza = (const float*)d_in[3];
    const float* wzb = (const float*)d_in[4];
    const float* ba  = (const float*)d_in[5];
    const float* bb  = (const float*)d_in[6];
    float* out = (float*)d_out;

    cudaFuncSetAttribute(gemm_kernel,
                         cudaFuncAttributeMaxDynamicSharedMemorySize, SMEM_BYTES);

    prep_w_kernel<<<dim3(D_ / 32, HD_ / 32, 4), dim3(32, 8)>>>(wka, wkb, wza, wzb);
    gemm_kernel<<<(NTOK / BM) * (NCOL / BN), 256, SMEM_BYTES>>>(h);

    int dup = (out_size >= 2 * OUT_ELEMS) ? 1 : 0;
    epilogue_kernel<<<OUT_ELEMS / 2 / 256, 256>>>(ba, bb, out, dup);
}

// round 11
// speedup vs baseline: 2.6020x; 1.0001x over previous
#include <cuda_runtime.h>
#include <cuda_fp16.h>
#include <cstdint>

// ---------------- problem constants -------------------------------------
#define B_    4
#define S_    8192
#define D_    2048
#define HD_   128
#define NTOK  (B_ * S_)            // 32768 tokens
#define NCOL  512                  // 4 projections * HD
#define NBLK  (B_ * (S_ / 4))      // 8192 output blocks
#define OUT_ELEMS (NBLK * HD_)     // 1048576

// GEMM tiling
#define BM 64
#define BN 256
#define BK 64
#define NKC (D_ / BK)              // 32 k-chunks

// ---------------- scratch (static device globals) ------------------------
__device__ __half g_Wt[NCOL * D_];                // 2 MB, K-major fp16 weights
__device__ __half g_C[(size_t)NTOK * NCOL];       // 32 MB GEMM output (fp16)

// ---------------- helpers ------------------------------------------------
__device__ __forceinline__ uint32_t smem_to_u32(const void* p) {
    uint32_t a;
    asm("{ .reg .u64 t; cvta.to.shared.u64 t, %1; cvt.u32.u64 %0, t; }"
        : "=r"(a) : "l"(p));
    return a;
}

// pack (k0, k1) -> f16x2 with k0 in the low half
__device__ __forceinline__ uint32_t pack2(float k0, float k1) {
    uint32_t r;
    asm("cvt.rn.f16x2.f32 %0, %1, %2;" : "=r"(r) : "f"(k1), "f"(k0));
    return r;
}

#define CP_ASYNC16(dst_u32, src_ptr) \
    asm volatile("cp.async.cg.shared.global [%0], [%1], 16;" \
                 :: "r"(dst_u32), "l"(src_ptr) : "memory")
#define CP_ASYNC_COMMIT() asm volatile("cp.async.commit_group;" ::: "memory")
#define CP_ASYNC_WAIT0()  asm volatile("cp.async.wait_group 0;" ::: "memory")

#define MMA_FP16(d, a, b) \
    asm volatile("mma.sync.aligned.m16n8k16.row.col.f32.f16.f16.f32 " \
                 "{%0,%1,%2,%3}, {%4,%5,%6,%7}, {%8,%9}, {%0,%1,%2,%3};" \
                 : "+f"((d)[0]), "+f"((d)[1]), "+f"((d)[2]), "+f"((d)[3]) \
                 : "r"((a)[0]), "r"((a)[1]), "r"((a)[2]), "r"((a)[3]), \
                   "r"((b)[0]), "r"((b)[1]))

#define LDMATRIX_X4(r0, r1, r2, r3, addr) \
    asm volatile("ldmatrix.sync.aligned.m8n8.x4.shared.b16 {%0,%1,%2,%3}, [%4];" \
                 : "=r"(r0), "=r"(r1), "=r"(r2), "=r"(r3) : "r"(addr))

// ---------------- smem layout (bytes): fp16 tiles, 128B rows padded to 144B
#define ROWB    144
#define A_PLANE (64 * ROWB)                // 9216 B
#define B_PLANE (256 * ROWB)               // 36864 B
#define STAGE   (A_PLANE + B_PLANE)        // 46080 B
#define OFF_A   0
#define OFF_B   A_PLANE
#define SMEM_BYTES (2 * STAGE)             // 92160 B

// ---------------- kernel 1: coalesced fp16 transpose of weights ----------
// g_Wt[n, k] = w_mat[k, j],  n = mat*128 + j
__global__ void prep_w_kernel(const float* __restrict__ wka,
                              const float* __restrict__ wkb,
                              const float* __restrict__ wza,
                              const float* __restrict__ wzb)
{
    __shared__ float tile[32][33];
    const int mat = blockIdx.z;
    const float* w = (mat == 0) ? wka : (mat == 1) ? wkb : (mat == 2) ? wza : wzb;
    const int k0 = blockIdx.x * 32;
    const int j0 = blockIdx.y * 32;
    const int tx = threadIdx.x;       // 0..31
    const int ty = threadIdx.y;       // 0..7

    #pragma unroll
    for (int i = 0; i < 32; i += 8)
        tile[ty + i][tx] = w[(size_t)(k0 + ty + i) * HD_ + j0 + tx];
    __syncthreads();
    #pragma unroll
    for (int i = 0; i < 32; i += 8)
        g_Wt[(size_t)(mat * HD_ + j0 + ty + i) * D_ + k0 + tx] =
            __float2half_rn(tile[tx][ty + i]);
}

// ---------------- kernel 2: pipelined fp16 mma.sync GEMM -----------------
// C[t, 0:512] = h[t, :] @ [Wkva | Wkvb | Wza | Wzb]
__global__ void __launch_bounds__(256, 2)
gemm_kernel(const float* __restrict__ h)
{
    extern __shared__ char sm[];
    const uint32_t smem_base = smem_to_u32(sm);

    const int tid    = threadIdx.x;
    const int lane   = tid & 31;
    const int wid    = tid >> 5;
    const int warp_m = wid >> 2;          // 0..1  (32 rows each)
    const int warp_n = wid & 3;           // 0..3  (64 cols each)

    const int t0 = (int)(blockIdx.x >> 1) * BM;
    const int n0 = (int)(blockIdx.x & 1) * BN;

    // A load coords: thread covers 16 contiguous k, one row
    const int arow = tid >> 2;            // 0..63
    const int akc  = tid & 3;             // 16-element k-chunk within 64
    const float* hrow = h + (size_t)(t0 + arow) * D_ + akc * 16;
    const uint32_t a_sts = (uint32_t)(arow * ROWB + akc * 32);

    uint32_t qa[8];

    // quantize 16 floats from hrow+off into qa
    auto loadquantA = [&](int koff) {
        #pragma unroll
        for (int i = 0; i < 4; ++i) {
            float4 v = *(const float4*)(hrow + koff + i * 4);
            qa[2 * i]     = pack2(v.x, v.y);
            qa[2 * i + 1] = pack2(v.z, v.w);
        }
    };

    // -------- prologue: stage 0 --------
    {
        loadquantA(0);
        #pragma unroll
        for (int j = 0; j < 8; ++j) {
            int e = tid + j * 256;
            int row = e >> 3, kc = e & 7;
            uint32_t dst = smem_base + OFF_B + (uint32_t)(row * ROWB + kc * 16);
            CP_ASYNC16(dst, g_Wt + (size_t)(n0 + row) * D_ + kc * 8);
        }
        CP_ASYNC_COMMIT();
        *(uint4*)(sm + OFF_A + a_sts)      = *(uint4*)(qa);
        *(uint4*)(sm + OFF_A + a_sts + 16) = *(uint4*)(qa + 4);
        CP_ASYNC_WAIT0();
        __syncthreads();
    }

    float acc[2][8][4];
    #pragma unroll
    for (int mt = 0; mt < 2; ++mt)
        #pragma unroll
        for (int nt = 0; nt < 8; ++nt)
            #pragma unroll
            for (int i = 0; i < 4; ++i) acc[mt][nt][i] = 0.0f;

    // ---- ldmatrix per-lane base addresses (stage offset added at use) ----
    // A tiles (m16k16, x4): lanes 0-7 rows m0-7 +0B; 8-15 rows m8-15 +0B;
    //                       16-23 rows m0-7 +16B; 24-31 rows m8-15 +16B
    const int aL_row = (lane & 7) + 8 * ((lane >> 3) & 1);
    const int aL_off = 16 * ((lane >> 4) & 1);
    uint32_t a_addr[2];
    #pragma unroll
    for (int mt = 0; mt < 2; ++mt)
        a_addr[mt] = smem_base + OFF_A +
                     (uint32_t)((warp_m * 32 + mt * 16 + aL_row) * ROWB + aL_off);

    // B tiles (two n8k16 per x4): matrices {nt+0B, nt+16B, nt+1+0B, nt+1+16B}
    const int bL_row = (lane & 7) + 8 * ((lane >> 4) & 1);   // which nt of the pair
    const int bL_off = 16 * ((lane >> 3) & 1);
    uint32_t b_addr[4];
    #pragma unroll
    for (int j = 0; j < 4; ++j)
        b_addr[j] = smem_base + OFF_B +
                    (uint32_t)((warp_n * 64 + j * 16 + bL_row) * ROWB + bL_off);

    for (int c = 0; c < NKC; ++c) {
        const int sb = (c & 1) * STAGE;
        const int nb = sb ^ STAGE;

        if (c + 1 < NKC) {
            const int k1 = (c + 1) * BK;
            loadquantA(k1);
            #pragma unroll
            for (int j = 0; j < 8; ++j) {
                int e = tid + j * 256;
                int row = e >> 3, kc = e & 7;
                uint32_t dst = smem_base + nb + OFF_B + (uint32_t)(row * ROWB + kc * 16);
                CP_ASYNC16(dst, g_Wt + (size_t)(n0 + row) * D_ + k1 + kc * 8);
            }
            CP_ASYNC_COMMIT();
        }

        // -------- compute on stage sb: 4 k16-steps --------
        #pragma unroll
        for (int ks = 0; ks < 4; ++ks) {
            const uint32_t ko = (uint32_t)sb + ks * 32;
            uint32_t af[2][4], bf[8][2];
            LDMATRIX_X4(af[0][0], af[0][1], af[0][2], af[0][3], a_addr[0] + ko);
            LDMATRIX_X4(af[1][0], af[1][1], af[1][2], af[1][3], a_addr[1] + ko);
            #pragma unroll
            for (int j = 0; j < 4; ++j)
                LDMATRIX_X4(bf[2 * j][0], bf[2 * j][1],
                            bf[2 * j + 1][0], bf[2 * j + 1][1], b_addr[j] + ko);
            #pragma unroll
            for (int mt = 0; mt < 2; ++mt)
                #pragma unroll
                for (int nt = 0; nt < 8; ++nt)
                    MMA_FP16(acc[mt][nt], af[mt], bf[nt]);
        }

        if (c + 1 < NKC) {
            *(uint4*)(sm + nb + OFF_A + a_sts)      = *(uint4*)(qa);
            *(uint4*)(sm + nb + OFF_A + a_sts + 16) = *(uint4*)(qa + 4);
            CP_ASYNC_WAIT0();
        }
        __syncthreads();
    }

    // -------- writeback (fp16) --------
    const int fr = lane >> 2;
    #pragma unroll
    for (int mt = 0; mt < 2; ++mt) {
        int r0 = t0 + warp_m * 32 + mt * 16 + fr;
        #pragma unroll
        for (int nt = 0; nt < 8; ++nt) {
            int cb = n0 + warp_n * 64 + nt * 8 + (lane & 3) * 2;
            *(uint32_t*)(g_C + (size_t)r0 * NCOL + cb) =
                pack2(acc[mt][nt][0], acc[mt][nt][1]);
            *(uint32_t*)(g_C + (size_t)(r0 + 8) * NCOL + cb) =
                pack2(acc[mt][nt][2], acc[mt][nt][3]);
        }
    }
}

// ---------------- kernel 3: masked softmax compression (half2) -----------
// C columns: [0,128)=c_a, [128,256)=c_b, [256,384)=z_a, [384,512)=z_b
__global__ void epilogue_kernel(const float* __restrict__ b_a,
                                const float* __restrict__ b_b,
                                float* __restrict__ out, int dup)
{
    int g2 = blockIdx.x * blockDim.x + threadIdx.x;   // 0..524287 (pairs)
    int d  = (g2 & 63) * 2;    // even feature index
    int bi = g2 >> 6;          // global block id 0..8191
    int i  = bi & 2047;        // block within batch
    int b  = bi >> 11;         // batch
    int t0 = b * S_ + i * 4;   // first token of current block

    float2 logit[8], val[8];
    const bool has_prev = (i > 0);
    #pragma unroll
    for (int j = 0; j < 4; ++j) {
        float2 bb2 = *(const float2*)(b_b + j * 128 + d);
        float2 ba2 = *(const float2*)(b_a + j * 128 + d);
        if (has_prev) {
            const __half* Cp = g_C + (size_t)(t0 - 4 + j) * NCOL;
            float2 z = __half22float2(*(const __half2*)(Cp + 384 + d));
            float2 v = __half22float2(*(const __half2*)(Cp + 128 + d));
            logit[j] = make_float2(z.x + bb2.x, z.y + bb2.y);
            val[j]   = v;
        } else {
            logit[j] = make_float2(-3.0e38f, -3.0e38f);
            val[j]   = make_float2(0.0f, 0.0f);
        }
        const __half* Cc = g_C + (size_t)(t0 + j) * NCOL;
        float2 z = __half22float2(*(const __half2*)(Cc + 256 + d));
        float2 v = __half22float2(*(const __half2*)(Cc + d));
        logit[4 + j] = make_float2(z.x + ba2.x, z.y + ba2.y);
        val[4 + j]   = v;
    }
    float mx0 = logit[0].x, mx1 = logit[0].y;
    #pragma unroll
    for (int j = 1; j < 8; ++j) {
        mx0 = fmaxf(mx0, logit[j].x);
        mx1 = fmaxf(mx1, logit[j].y);
    }
    float s0 = 0.0f, s1 = 0.0f, a0 = 0.0f, a1 = 0.0f;
    #pragma unroll
    for (int j = 0; j < 8; ++j) {
        float e0 = __expf(logit[j].x - mx0);
        float e1 = __expf(logit[j].y - mx1);
        s0 += e0; s1 += e1;
        a0 += e0 * val[j].x; a1 += e1 * val[j].y;
    }
    float2 r = make_float2(a0 / s0, a1 / s1);
    int o = bi * 128 + d;
    *(float2*)(out + o) = r;
    if (dup) *(float2*)(out + o + OUT_ELEMS) = r;
}

// ---------------- launch ------------------------------------------------
extern "C" void kernel_launch(void* const* d_in, const int* in_sizes, int n_in,
                              void* d_out, int out_size)
{
    const float* h   = (const float*)d_in[0];
    const float* wka = (const float*)d_in[1];
    const float* wkb = (const float*)d_in[2];
    const float* wza = (const float*)d_in[3];
    const float* wzb = (const float*)d_in[4];
    const float* ba  = (const float*)d_in[5];
    const float* bb  = (const float*)d_in[6];
    float* out = (float*)d_out;

    cudaFuncSetAttribute(gemm_kernel,
                         cudaFuncAttributeMaxDynamicSharedMemorySize, SMEM_BYTES);

    prep_w_kernel<<<dim3(D_ / 32, HD_ / 32, 4), dim3(32, 8)>>>(wka, wkb, wza, wzb);
    gemm_kernel<<<(NTOK / BM) * (NCOL / BN), 256, SMEM_BYTES>>>(h);

    int dup = (out_size >= 2 * OUT_ELEMS) ? 1 : 0;
    epilogue_kernel<<<OUT_ELEMS / 2 / 256, 256>>>(ba, bb, out, dup);
}